// round 2
// baseline (speedup 1.0000x reference)
#include <cuda_runtime.h>

// Problem constants
#define BATCH   2
#define NPTS    (2*16384*32)   // 1,048,576 points
#define HID     64
#define OUTC    33
#define PTSB    128            // points per block

// Transposed triplane scratch: (B*3, H, W, 32ch) channel-last, 50.3 MB
__device__ float g_tp[(size_t)BATCH * 3 * 256 * 256 * 32];

// ---------------------------------------------------------------------------
// Kernel 1: transpose (B, 96, H, W) -> (B*3, H, W, 32)
// ---------------------------------------------------------------------------
__global__ void transpose_k(const float* __restrict__ tri) {
    __shared__ float sh[32][257];
    int slice = blockIdx.x;         // (bp)*256 + y
    int y  = slice & 255;
    int bp = slice >> 8;
    int tx = threadIdx.x;

    const float* src = tri + (size_t)bp * 32 * 65536 + (size_t)y * 256;
    #pragma unroll
    for (int c = 0; c < 32; c++)
        sh[c][tx] = src[(size_t)c * 65536 + tx];
    __syncthreads();

    float* dst = g_tp + ((size_t)bp * 65536 + (size_t)y * 256) * 32;
    #pragma unroll
    for (int i = 0; i < 32; i++) {
        int x = i * 8 + (tx >> 5);
        int c = tx & 31;
        dst[x * 32 + c] = sh[c][x];
    }
}

// ---------------------------------------------------------------------------
// Kernel 2: sample + MLP, 4-point / 8-neuron register blocking.
//   Shared layout (float offsets):
//     SW0  [32][64] permuted:  sW0p[c][8q+j] = W0[c][8j+q]
//     SW1  [64][64] permuted
//     SW2  [64][40] permuted:  sW2p[c][5q+j] = W2[c][8j+q] (0 if >=33)
//     SB0/SB1[64] permuted, SB2[40] permuted
//     SPT  [128*3] points
//     SFT  [32][132]  feat transposed: sftT[c][pt]
//     HBUF [64][132]  h0 then h1 (transposed, reused)
//     SOUT [128][36]  output staging (row-major, padded)
// ---------------------------------------------------------------------------
#define SW0   0
#define SW1   2048
#define SW2   6144
#define SB0   8704
#define SB1   8768
#define SB2   8832
#define SPT   8872
#define SFT   9256
#define HBUF  13480
#define SOUT  21928
#define SMEMF 26536

__device__ __forceinline__ float lrelu(float v) { return fmaxf(v, 0.01f * v); }

__global__ __launch_bounds__(256, 2) void decode_k(
    const float* __restrict__ pts,
    const float* __restrict__ W0, const float* __restrict__ b0,
    const float* __restrict__ W1, const float* __restrict__ b1,
    const float* __restrict__ W2, const float* __restrict__ b2,
    float* __restrict__ out)
{
    extern __shared__ float sm[];
    int tid = threadIdx.x;
    int n0  = blockIdx.x * PTSB;

    // ---- load & permute weights, load points ----
    for (int i = tid; i < 2048; i += 256) {           // W0 [32][64]
        int c = i >> 6, t = i & 63, q = t >> 3, j = t & 7;
        sm[SW0 + i] = W0[c * 64 + 8 * j + q];
    }
    for (int i = tid; i < 4096; i += 256) {           // W1 [64][64]
        int c = i >> 6, t = i & 63, q = t >> 3, j = t & 7;
        sm[SW1 + i] = W1[c * 64 + 8 * j + q];
    }
    for (int i = tid; i < 64 * 40; i += 256) {        // W2 [64][40]
        int c = i / 40, t = i - c * 40, q = t / 5, j = t - q * 5;
        int n = 8 * j + q;
        sm[SW2 + i] = (n < OUTC) ? W2[c * OUTC + n] : 0.f;
    }
    if (tid < 64) {
        int q = tid >> 3, j = tid & 7;
        sm[SB0 + tid] = b0[8 * j + q];
        sm[SB1 + tid] = b1[8 * j + q];
    }
    if (tid < 40) {
        int q = tid / 5, j = tid - q * 5;
        int n = 8 * j + q;
        sm[SB2 + tid] = (n < OUTC) ? b2[n] : 0.f;
    }
    for (int i = tid; i < PTSB * 3; i += 256)
        sm[SPT + i] = pts[(size_t)n0 * 3 + i];
    __syncthreads();

    int bb = n0 >> 19;
    const float* plane_base = g_tp + (size_t)bb * 3 * 2097152;

    // ---- Phase A: sampling -> sftT[c][pt] ----
    {
        int cg = tid & 7;        // channel group (4 ch)
        int p0 = tid >> 3;       // 0..31
        #pragma unroll 1
        for (int pass = 0; pass < 4; pass++) {
            int pl = pass * 32 + p0;
            float px = sm[SPT + pl * 3 + 0];
            float py = sm[SPT + pl * 3 + 1];
            float pz = sm[SPT + pl * 3 + 2];
            float ax = 0.f, ay = 0.f, az = 0.f, aw = 0.f;
            #pragma unroll
            for (int plane = 0; plane < 3; plane++) {
                float gx = (plane == 2) ? py : px;    // xy, xz, yz
                float gy = (plane == 0) ? py : pz;
                float fx = fmaf(gx, 128.f, 127.5f);
                float fy = fmaf(gy, 128.f, 127.5f);
                float x0f = floorf(fx), y0f = floorf(fy);
                float wx = fx - x0f, wy = fy - y0f;
                int ix0 = (int)x0f, iy0 = (int)y0f;
                float w00 = (1.f - wx) * (1.f - wy);
                float w10 = wx * (1.f - wy);
                float w01 = (1.f - wx) * wy;
                float w11 = wx * wy;
                const float* pb = plane_base + (size_t)plane * 2097152 + cg * 4;
                #pragma unroll
                for (int k = 0; k < 4; k++) {
                    int ix = ix0 + (k & 1);
                    int iy = iy0 + (k >> 1);
                    float w = (k == 0) ? w00 : (k == 1) ? w10 : (k == 2) ? w01 : w11;
                    if ((unsigned)ix < 256u && (unsigned)iy < 256u) {
                        const float4 v = *(const float4*)(pb + ((size_t)((iy << 8) + ix)) * 32);
                        ax = fmaf(w, v.x, ax);
                        ay = fmaf(w, v.y, ay);
                        az = fmaf(w, v.z, az);
                        aw = fmaf(w, v.w, aw);
                    }
                }
            }
            sm[SFT + (cg * 4 + 0) * 132 + pl] = ax;
            sm[SFT + (cg * 4 + 1) * 132 + pl] = ay;
            sm[SFT + (cg * 4 + 2) * 132 + pl] = az;
            sm[SFT + (cg * 4 + 3) * 132 + pl] = aw;
        }
    }
    __syncthreads();

    // ---- Phase B: MLP, thread = (g: 4 points, q: 8-neuron slice) ----
    int g = tid >> 3;            // 0..31 -> points 4g..4g+3
    int q = tid & 7;

    // Layer 0: 32 -> 64
    float acc0[4][8];
    #pragma unroll
    for (int j = 0; j < 8; j++) {
        float bj = sm[SB0 + 8 * q + j];
        #pragma unroll
        for (int p = 0; p < 4; p++) acc0[p][j] = bj;
    }
    #pragma unroll 4
    for (int c = 0; c < 32; c++) {
        const float4 xv = *(const float4*)&sm[SFT + c * 132 + 4 * g];
        const float4 wa = *(const float4*)&sm[SW0 + c * 64 + 8 * q];
        const float4 wb = *(const float4*)&sm[SW0 + c * 64 + 8 * q + 4];
        float xs[4] = {xv.x, xv.y, xv.z, xv.w};
        #pragma unroll
        for (int p = 0; p < 4; p++) {
            acc0[p][0] = fmaf(xs[p], wa.x, acc0[p][0]);
            acc0[p][1] = fmaf(xs[p], wa.y, acc0[p][1]);
            acc0[p][2] = fmaf(xs[p], wa.z, acc0[p][2]);
            acc0[p][3] = fmaf(xs[p], wa.w, acc0[p][3]);
            acc0[p][4] = fmaf(xs[p], wb.x, acc0[p][4]);
            acc0[p][5] = fmaf(xs[p], wb.y, acc0[p][5]);
            acc0[p][6] = fmaf(xs[p], wb.z, acc0[p][6]);
            acc0[p][7] = fmaf(xs[p], wb.w, acc0[p][7]);
        }
    }
    // lrelu + store h0 transposed: row = 8j+q
    #pragma unroll
    for (int j = 0; j < 8; j++) {
        float4 v;
        v.x = lrelu(acc0[0][j]);
        v.y = lrelu(acc0[1][j]);
        v.z = lrelu(acc0[2][j]);
        v.w = lrelu(acc0[3][j]);
        *(float4*)&sm[HBUF + (8 * j + q) * 132 + 4 * g] = v;
    }
    __syncthreads();

    // Layer 1: 64 -> 64
    float acc1[4][8];
    #pragma unroll
    for (int j = 0; j < 8; j++) {
        float bj = sm[SB1 + 8 * q + j];
        #pragma unroll
        for (int p = 0; p < 4; p++) acc1[p][j] = bj;
    }
    #pragma unroll 4
    for (int c = 0; c < 64; c++) {
        const float4 xv = *(const float4*)&sm[HBUF + c * 132 + 4 * g];
        const float4 wa = *(const float4*)&sm[SW1 + c * 64 + 8 * q];
        const float4 wb = *(const float4*)&sm[SW1 + c * 64 + 8 * q + 4];
        float xs[4] = {xv.x, xv.y, xv.z, xv.w};
        #pragma unroll
        for (int p = 0; p < 4; p++) {
            acc1[p][0] = fmaf(xs[p], wa.x, acc1[p][0]);
            acc1[p][1] = fmaf(xs[p], wa.y, acc1[p][1]);
            acc1[p][2] = fmaf(xs[p], wa.z, acc1[p][2]);
            acc1[p][3] = fmaf(xs[p], wa.w, acc1[p][3]);
            acc1[p][4] = fmaf(xs[p], wb.x, acc1[p][4]);
            acc1[p][5] = fmaf(xs[p], wb.y, acc1[p][5]);
            acc1[p][6] = fmaf(xs[p], wb.z, acc1[p][6]);
            acc1[p][7] = fmaf(xs[p], wb.w, acc1[p][7]);
        }
    }
    __syncthreads();   // all h0 readers done before overwriting HBUF
    #pragma unroll
    for (int j = 0; j < 8; j++) {
        float4 v;
        v.x = lrelu(acc1[0][j]);
        v.y = lrelu(acc1[1][j]);
        v.z = lrelu(acc1[2][j]);
        v.w = lrelu(acc1[3][j]);
        *(float4*)&sm[HBUF + (8 * j + q) * 132 + 4 * g] = v;
    }
    __syncthreads();

    // Layer 2: 64 -> 33 (thread owns outs 8j+q, j<5)
    float acc2[4][5];
    #pragma unroll
    for (int j = 0; j < 5; j++) {
        float bj = sm[SB2 + 5 * q + j];
        #pragma unroll
        for (int p = 0; p < 4; p++) acc2[p][j] = bj;
    }
    #pragma unroll 4
    for (int c = 0; c < 64; c++) {
        const float4 xv = *(const float4*)&sm[HBUF + c * 132 + 4 * g];
        float xs[4] = {xv.x, xv.y, xv.z, xv.w};
        #pragma unroll
        for (int j = 0; j < 5; j++) {
            float w = sm[SW2 + c * 40 + 5 * q + j];
            #pragma unroll
            for (int p = 0; p < 4; p++)
                acc2[p][j] = fmaf(xs[p], w, acc2[p][j]);
        }
    }
    #pragma unroll
    for (int j = 0; j < 5; j++) {
        int n = 8 * j + q;
        if (n < OUTC) {
            #pragma unroll
            for (int p = 0; p < 4; p++)
                sm[SOUT + (4 * g + p) * 36 + n] = acc2[p][j];
        }
    }
    __syncthreads();

    // ---- Phase C: coalesced copy-out ----
    for (int i = tid; i < PTSB * OUTC; i += 256) {
        int p = i / OUTC;
        int o = i - p * OUTC;
        out[(size_t)n0 * OUTC + i] = sm[SOUT + p * 36 + o];
    }
}

// ---------------------------------------------------------------------------
extern "C" void kernel_launch(void* const* d_in, const int* in_sizes, int n_in,
                              void* d_out, int out_size) {
    const float* tri = (const float*)d_in[0];
    const float* pts = (const float*)d_in[1];
    const float* W0  = (const float*)d_in[2];
    const float* b0  = (const float*)d_in[3];
    const float* W1  = (const float*)d_in[4];
    const float* b1  = (const float*)d_in[5];
    const float* W2  = (const float*)d_in[6];
    const float* b2  = (const float*)d_in[7];
    float* out = (float*)d_out;

    cudaFuncSetAttribute(decode_k, cudaFuncAttributeMaxDynamicSharedMemorySize,
                         SMEMF * 4);

    transpose_k<<<BATCH * 3 * 256, 256>>>(tri);
    decode_k<<<NPTS / PTSB, 256, SMEMF * 4>>>(pts, W0, b0, W1, b1, W2, b2, out);
}

// round 4
// speedup vs baseline: 2.7917x; 2.7917x over previous
#include <cuda_runtime.h>
#include <cuda_fp16.h>
#include <cstdint>

#define NPTS  (2*16384*32)    // 1,048,576
#define PTSB  128             // points per block
#define NBLK  (NPTS/PTSB)     // 8192

// transposed triplane (B*3, H, W, 32ch) channel-last, 50.3MB
__device__ float g_tp[(size_t)2*3*256*256*32];
// fragment-ordered fp16 weights: L0 512, L1 1024, L2 640 frags (uint2 each)
__device__ uint2 g_wf[2176];
#define WF_L0 0
#define WF_L1 512
#define WF_L2 1536

__device__ __forceinline__ uint32_t pkh(__half a, __half b) {
    __half2 h2 = __halves2half2(a, b);
    return *reinterpret_cast<uint32_t*>(&h2);
}

// ---------------------------------------------------------------------------
// Kernel 0: pack weights into per-lane mma B fragments (fp16).
// Fragment (layer, kt, nt, lane): n = nt*8 + lane/4, k0 = kt*16 + 2*(lane%4)
//   reg0 = {W[k0][n], W[k0+1][n]}  reg1 = {W[k0+8][n], W[k0+9][n]}
// ---------------------------------------------------------------------------
__global__ void prep_w(const float* __restrict__ W0, const float* __restrict__ W1,
                       const float* __restrict__ W2) {
    int idx = blockIdx.x * blockDim.x + threadIdx.x;
    if (idx >= 2176) return;
    int layer, frag;
    if (idx < 512)       { layer = 0; frag = idx; }
    else if (idx < 1536) { layer = 1; frag = idx - 512; }
    else                 { layer = 2; frag = idx - 1536; }
    int lane = frag & 31;
    int tb   = frag >> 5;
    int nt   = (layer == 2) ? (tb % 5) : (tb & 7);
    int kt   = (layer == 2) ? (tb / 5) : (tb >> 3);
    int n  = nt * 8 + (lane >> 2);
    int k0 = kt * 16 + 2 * (lane & 3);

    float wv[4];
    #pragma unroll
    for (int j = 0; j < 4; j++) {
        int k = k0 + ((j & 1) ? 1 : 0) + ((j >> 1) ? 8 : 0);
        float w;
        if (layer == 0)      w = W0[k * 64 + n];
        else if (layer == 1) w = W1[k * 64 + n];
        else                 w = (n < 33) ? W2[k * 33 + n] : 0.f;
        wv[j] = w;
    }
    uint2 o;
    o.x = pkh(__float2half_rn(wv[0]), __float2half_rn(wv[1]));
    o.y = pkh(__float2half_rn(wv[2]), __float2half_rn(wv[3]));
    g_wf[idx] = o;
}

// ---------------------------------------------------------------------------
// Kernel 1: transpose (B, 96, H, W) -> (B*3, H, W, 32) channel-last
// ---------------------------------------------------------------------------
__global__ void transpose_k(const float* __restrict__ tri) {
    __shared__ float sh[32][257];
    int slice = blockIdx.x;
    int y = slice & 255, bp = slice >> 8, tx = threadIdx.x;
    const float* src = tri + (size_t)bp * 32 * 65536 + (size_t)y * 256;
    #pragma unroll
    for (int c = 0; c < 32; c++) sh[c][tx] = src[(size_t)c * 65536 + tx];
    __syncthreads();
    float* dst = g_tp + ((size_t)bp * 65536 + (size_t)y * 256) * 32;
    #pragma unroll
    for (int i = 0; i < 32; i++) {
        int x = i * 8 + (tx >> 5), c = tx & 31;
        dst[x * 32 + c] = sh[c][x];
    }
}

// ---------------------------------------------------------------------------
// mma.sync m16n8k16 fp16 -> f32
// ---------------------------------------------------------------------------
__device__ __forceinline__ void mma16816(float* c, const uint32_t* a, uint2 b) {
    asm volatile(
        "mma.sync.aligned.m16n8k16.row.col.f32.f16.f16.f32 "
        "{%0,%1,%2,%3}, {%4,%5,%6,%7}, {%8,%9}, {%0,%1,%2,%3};"
        : "+f"(c[0]), "+f"(c[1]), "+f"(c[2]), "+f"(c[3])
        : "r"(a[0]), "r"(a[1]), "r"(a[2]), "r"(a[3]), "r"(b.x), "r"(b.y));
}

// convert float pair -> fp16x2 hi and residual lo
__device__ __forceinline__ void cvt_hl(float x, float y, uint32_t& hi, uint32_t& lo) {
    __half2 h = __floats2half2_rn(x, y);
    float2 hf = __half22float2(h);
    __half2 l = __floats2half2_rn(x - hf.x, y - hf.y);
    hi = *reinterpret_cast<uint32_t*>(&h);
    lo = *reinterpret_cast<uint32_t*>(&l);
}

__device__ __forceinline__ float lrelu(float v) { return fmaxf(v, 0.01f * v); }

// ---------------------------------------------------------------------------
// Kernel 2: sample + HMMA MLP, 256 threads, 128 points per block
// ---------------------------------------------------------------------------
__global__ __launch_bounds__(256, 2) void decode_k(
    const float* __restrict__ pts,
    const float* __restrict__ b0, const float* __restrict__ b1,
    const float* __restrict__ b2, float* __restrict__ out)
{
    __shared__ uint2 s_wf[2176];
    __shared__ float s_bias[168];     // b0[0:64) b1[64:128) b2pad[128:168)
    __shared__ float s_pts[PTSB * 3];
    __shared__ float s_fs[PTSB * 36]; // feat (in), then aliased as out staging

    int tid  = threadIdx.x;
    int lane = tid & 31;
    int w    = tid >> 5;
    int n0   = blockIdx.x * PTSB;

    for (int i = tid; i < 2176; i += 256) s_wf[i] = g_wf[i];
    if (tid < 64) { s_bias[tid] = b0[tid]; s_bias[64 + tid] = b1[tid]; }
    if (tid < 40) s_bias[128 + tid] = (tid < 33) ? b2[tid] : 0.f;
    for (int i = tid; i < PTSB * 3; i += 256) s_pts[i] = pts[(size_t)n0 * 3 + i];
    __syncthreads();

    // ---- Phase A: sampling (8 lanes/pt, 32 pts/pass, 4 passes) ----
    {
        int bb = n0 >> 19;
        const float* plane_base = g_tp + (size_t)bb * 3 * 2097152;
        int cg = tid & 7, g = tid >> 3;
        #pragma unroll 1
        for (int pass = 0; pass < 4; pass++) {
            int pl = pass * 32 + g;
            float px = s_pts[pl * 3 + 0];
            float py = s_pts[pl * 3 + 1];
            float pz = s_pts[pl * 3 + 2];
            float ax = 0.f, ay = 0.f, az = 0.f, aw = 0.f;
            #pragma unroll
            for (int plane = 0; plane < 3; plane++) {
                float gx = (plane == 2) ? py : px;
                float gy = (plane == 0) ? py : pz;
                float fx = fmaf(gx, 128.f, 127.5f);
                float fy = fmaf(gy, 128.f, 127.5f);
                float x0f = floorf(fx), y0f = floorf(fy);
                float wx = fx - x0f, wy = fy - y0f;
                int ix0 = (int)x0f, iy0 = (int)y0f;
                float w00 = (1.f - wx) * (1.f - wy);
                float w10 = wx * (1.f - wy);
                float w01 = (1.f - wx) * wy;
                float w11 = wx * wy;
                const float* pb = plane_base + (size_t)plane * 2097152 + cg * 4;
                #pragma unroll
                for (int k = 0; k < 4; k++) {
                    int ix = ix0 + (k & 1);
                    int iy = iy0 + (k >> 1);
                    float wgt = (k == 0) ? w00 : (k == 1) ? w10 : (k == 2) ? w01 : w11;
                    if ((unsigned)ix < 256u && (unsigned)iy < 256u) {
                        const float4 v = *(const float4*)(pb + ((size_t)((iy << 8) + ix)) * 32);
                        ax = fmaf(wgt, v.x, ax);
                        ay = fmaf(wgt, v.y, ay);
                        az = fmaf(wgt, v.z, az);
                        aw = fmaf(wgt, v.w, aw);
                    }
                }
            }
            *(float4*)&s_fs[pl * 36 + cg * 4] = make_float4(ax, ay, az, aw);
        }
    }
    __syncthreads();

    // ---- Phase B: MLP in registers (warp w owns points [16w, 16w+16)) ----
    {
        int r  = lane >> 2;
        int cq = lane & 3;
        int base = w * 16;

        uint32_t Ah[4][4], Al[4][4];

        // layer-0 A fragments from sampled features (fp32 -> fp16 hi/lo)
        #pragma unroll
        for (int kt = 0; kt < 2; kt++) {
            const float* f0 = &s_fs[(base + r) * 36 + kt * 16 + 2 * cq];
            const float* f1 = &s_fs[(base + r + 8) * 36 + kt * 16 + 2 * cq];
            float2 v00 = *(const float2*)f0;        // A[r][2c,2c+1]
            float2 v01 = *(const float2*)f1;        // A[r+8][..]
            float2 v10 = *(const float2*)(f0 + 8);  // A[r][2c+8,+9]
            float2 v11 = *(const float2*)(f1 + 8);
            cvt_hl(v00.x, v00.y, Ah[kt][0], Al[kt][0]);
            cvt_hl(v01.x, v01.y, Ah[kt][1], Al[kt][1]);
            cvt_hl(v10.x, v10.y, Ah[kt][2], Al[kt][2]);
            cvt_hl(v11.x, v11.y, Ah[kt][3], Al[kt][3]);
        }

        // ---- layer 0: K=32, N=64 ----
        float acc[8][4];
        #pragma unroll
        for (int nt = 0; nt < 8; nt++) {
            acc[nt][0] = acc[nt][1] = acc[nt][2] = acc[nt][3] = 0.f;
            #pragma unroll
            for (int kt = 0; kt < 2; kt++) {
                uint2 bfr = s_wf[WF_L0 + (kt * 8 + nt) * 32 + lane];
                mma16816(acc[nt], Ah[kt], bfr);
                mma16816(acc[nt], Al[kt], bfr);
            }
        }
        // bias + lrelu + convert to next A frags
        #pragma unroll
        for (int nt = 0; nt < 8; nt++) {
            float2 bv = *(const float2*)&s_bias[8 * nt + 2 * cq];
            acc[nt][0] = lrelu(acc[nt][0] + bv.x);
            acc[nt][1] = lrelu(acc[nt][1] + bv.y);
            acc[nt][2] = lrelu(acc[nt][2] + bv.x);
            acc[nt][3] = lrelu(acc[nt][3] + bv.y);
        }
        #pragma unroll
        for (int kt = 0; kt < 4; kt++) {
            cvt_hl(acc[2*kt][0],   acc[2*kt][1],   Ah[kt][0], Al[kt][0]);
            cvt_hl(acc[2*kt][2],   acc[2*kt][3],   Ah[kt][1], Al[kt][1]);
            cvt_hl(acc[2*kt+1][0], acc[2*kt+1][1], Ah[kt][2], Al[kt][2]);
            cvt_hl(acc[2*kt+1][2], acc[2*kt+1][3], Ah[kt][3], Al[kt][3]);
        }

        // ---- layer 1: K=64, N=64 ----
        float acc1[8][4];
        #pragma unroll
        for (int nt = 0; nt < 8; nt++) {
            acc1[nt][0] = acc1[nt][1] = acc1[nt][2] = acc1[nt][3] = 0.f;
            #pragma unroll
            for (int kt = 0; kt < 4; kt++) {
                uint2 bfr = s_wf[WF_L1 + (kt * 8 + nt) * 32 + lane];
                mma16816(acc1[nt], Ah[kt], bfr);
                mma16816(acc1[nt], Al[kt], bfr);
            }
        }
        #pragma unroll
        for (int nt = 0; nt < 8; nt++) {
            float2 bv = *(const float2*)&s_bias[64 + 8 * nt + 2 * cq];
            acc1[nt][0] = lrelu(acc1[nt][0] + bv.x);
            acc1[nt][1] = lrelu(acc1[nt][1] + bv.y);
            acc1[nt][2] = lrelu(acc1[nt][2] + bv.x);
            acc1[nt][3] = lrelu(acc1[nt][3] + bv.y);
        }
        #pragma unroll
        for (int kt = 0; kt < 4; kt++) {
            cvt_hl(acc1[2*kt][0],   acc1[2*kt][1],   Ah[kt][0], Al[kt][0]);
            cvt_hl(acc1[2*kt][2],   acc1[2*kt][3],   Ah[kt][1], Al[kt][1]);
            cvt_hl(acc1[2*kt+1][0], acc1[2*kt+1][1], Ah[kt][2], Al[kt][2]);
            cvt_hl(acc1[2*kt+1][2], acc1[2*kt+1][3], Ah[kt][3], Al[kt][3]);
        }

        // ---- layer 2: K=64, N=40 (33 valid) ----
        float acc2[5][4];
        #pragma unroll
        for (int nt = 0; nt < 5; nt++) {
            acc2[nt][0] = acc2[nt][1] = acc2[nt][2] = acc2[nt][3] = 0.f;
            #pragma unroll
            for (int kt = 0; kt < 4; kt++) {
                uint2 bfr = s_wf[WF_L2 + (kt * 5 + nt) * 32 + lane];
                mma16816(acc2[nt], Ah[kt], bfr);
                mma16816(acc2[nt], Al[kt], bfr);
            }
        }
        __syncwarp();   // all feat reads done before aliased staging writes
        #pragma unroll
        for (int nt = 0; nt < 5; nt++) {
            float2 bv = *(const float2*)&s_bias[128 + 8 * nt + 2 * cq];
            int nc = 8 * nt + 2 * cq;
            float* st0 = &s_fs[(base + r) * 36];
            float* st1 = &s_fs[(base + r + 8) * 36];
            if (nc < 33) {
                st0[nc] = acc2[nt][0] + bv.x;
                st1[nc] = acc2[nt][2] + bv.x;
            }
            if (nc + 1 < 33) {
                st0[nc + 1] = acc2[nt][1] + bv.y;
                st1[nc + 1] = acc2[nt][3] + bv.y;
            }
        }
    }
    __syncthreads();

    // ---- Phase C: coalesced copy-out (packed 33 floats/pt) ----
    float* dst = out + (size_t)n0 * 33;
    for (int i = tid; i < PTSB * 33; i += 256) {
        int p = i / 33;
        dst[i] = s_fs[p * 36 + (i - p * 33)];
    }
}

// ---------------------------------------------------------------------------
extern "C" void kernel_launch(void* const* d_in, const int* in_sizes, int n_in,
                              void* d_out, int out_size) {
    const float* tri = (const float*)d_in[0];
    const float* pts = (const float*)d_in[1];
    const float* W0  = (const float*)d_in[2];
    const float* b0  = (const float*)d_in[3];
    const float* W1  = (const float*)d_in[4];
    const float* b1  = (const float*)d_in[5];
    const float* W2  = (const float*)d_in[6];
    const float* b2  = (const float*)d_in[7];
    float* out = (float*)d_out;

    prep_w<<<9, 256>>>(W0, W1, W2);
    transpose_k<<<2 * 3 * 256, 256>>>(tri);
    decode_k<<<NBLK, 256>>>(pts, b0, b1, b2, out);
}